// round 15
// baseline (speedup 1.0000x reference)
#include <cuda_runtime.h>
#include <cuda_fp16.h>
#include <cstdint>

#define BATCH 512
#define NOISE 100
#define EMBD  50
#define NCLS  10
#define C1    256
#define C2    128

typedef unsigned long long ull;

// ---------------- scratch ----------------
__device__ __align__(16) __half g_a0[BATCH * 49 * 256];
__device__ __align__(16) __half g_a1[BATCH * 49 * 256];
__device__ __align__(16) __half g_a2[BATCH * 196 * C2];
__device__ __align__(16) float  g_embf[NCLS * 49 * 256];
__device__ __align__(16) float  g_embw[NCLS * 25 * 256];
// pair-packed weight fragments: uint4 = {frag(nt=2p) , frag(nt=2p+1)} per lane
__device__ __align__(16) uint4  g_W1[(size_t)NCLS * 16 * 25 * 16 * 32];
__device__ __align__(16) uint4  g_W2[(size_t)NCLS * 16 * 25 * 8 * 32];
__device__ int g_perm[BATCH];
__device__ int g_cnt[NCLS];
__device__ int g_off[NCLS];

__device__ __forceinline__ float lrelu(float x) { return x >= 0.f ? x : 0.3f * x; }

__device__ __forceinline__ ull splat2(float a) {
    ull d; unsigned ai = __float_as_uint(a);
    asm("mov.b64 %0, {%1, %1};" : "=l"(d) : "r"(ai));
    return d;
}
__device__ __forceinline__ void ffma2(ull& c, ull a, ull b) {
    asm("fma.rn.f32x2 %0, %1, %2, %3;" : "=l"(c) : "l"(a), "l"(b), "l"(c));
}
__device__ __forceinline__ float2 unpk(ull v) {
    unsigned lo, hi;
    asm("mov.b64 {%0, %1}, %2;" : "=r"(lo), "=r"(hi) : "l"(v));
    return make_float2(__uint_as_float(lo), __uint_as_float(hi));
}

#define CP_COMMIT() asm volatile("cp.async.commit_group;" ::: "memory")
#define CP_WAIT0()  asm volatile("cp.async.wait_group 0;" ::: "memory")

__device__ __forceinline__ void cp16(uint32_t saddr, const void* g) {
    asm volatile("cp.async.cg.shared.global [%0], [%1], 16;" :: "r"(saddr), "l"(g) : "memory");
}

#define LDSM4(a, addr) asm volatile( \
    "ldmatrix.sync.aligned.m8n8.x4.shared.b16 {%0,%1,%2,%3}, [%4];" \
    : "=r"(a[0]), "=r"(a[1]), "=r"(a[2]), "=r"(a[3]) : "r"(addr))

#define MMA2(d, a, bx_, by_) asm volatile( \
    "mma.sync.aligned.m16n8k16.row.col.f32.f16.f16.f32 " \
    "{%0,%1,%2,%3}, {%4,%5,%6,%7}, {%8,%9}, {%0,%1,%2,%3};" \
    : "+f"(d[0]), "+f"(d[1]), "+f"(d[2]), "+f"(d[3]) \
    : "r"(a[0]), "r"(a[1]), "r"(a[2]), "r"(a[3]), "r"(bx_), "r"(by_))

__device__ __forceinline__ uint32_t h2pack(float a, float b) {
    __half2 p = __halves2half2(__float2half(a), __float2half(b));
    return *(uint32_t*)&p;
}

// =====================================================================
__global__ __launch_bounds__(512) void k_bucket(const int* __restrict__ labels)
{
    __shared__ int scnt[NCLS], scur[NCLS];
    int t = threadIdx.x;
    if (t < NCLS) scnt[t] = 0;
    __syncthreads();
    int c = labels[t];
    atomicAdd(&scnt[c], 1);
    __syncthreads();
    if (t == 0) {
        int run = 0;
        for (int k = 0; k < NCLS; k++) { g_off[k] = run; scur[k] = run; g_cnt[k] = scnt[k]; run += scnt[k]; }
    }
    __syncthreads();
    int pos = atomicAdd(&scur[c], 1);
    g_perm[pos] = t;
}

// =====================================================================
// dense + BN + LReLU -> act0 fp16
// =====================================================================
__global__ __launch_bounds__(256) void k_dense(
    const float* __restrict__ noise, const int* __restrict__ labels,
    const float* __restrict__ emb,   const float* __restrict__ Wd,
    const float* __restrict__ bn_g,  const float* __restrict__ bn_b,
    const float* __restrict__ bn_m,  const float* __restrict__ bn_v)
{
    __shared__ __align__(8) float2 xs2[150 * 4];
    const int t  = threadIdx.x;
    const int bx = blockIdx.x;
    const int b0 = blockIdx.y * 8;

    for (int idx = t; idx < 8 * 150; idx += 256) {
        int s = idx / 150, k = idx - s * 150;
        int bb = b0 + s;
        float val = (k < NOISE) ? noise[bb * NOISE + k]
                                : emb[labels[bb] * EMBD + (k - NOISE)];
        ((float*)&xs2[k * 4 + (s >> 1)])[s & 1] = val;
    }
    __syncthreads();

    const int j = bx * 256 + t;
    ull acc2[4];
#pragma unroll
    for (int pr = 0; pr < 4; pr++) acc2[pr] = 0ull;
    for (int k = 0; k < 150; k++) {
        ull ws = splat2(Wd[k * 12544 + j]);
#pragma unroll
        for (int pr = 0; pr < 4; pr++) {
            ull a = *(const ull*)&xs2[k * 4 + pr];
            ffma2(acc2[pr], a, ws);
        }
    }
    const float sc = rsqrtf(bn_v[j] + 1e-3f) * bn_g[j];
    const float mm = bn_m[j];
    const float bb = bn_b[j];
#pragma unroll
    for (int pr = 0; pr < 4; pr++) {
        float2 v = unpk(acc2[pr]);
#pragma unroll
        for (int h2 = 0; h2 < 2; h2++) {
            float y = lrelu(((h2 ? v.y : v.x) - mm) * sc + bb);
            g_a0[(size_t)(b0 + pr * 2 + h2) * (49 * 256) + j] = __float2half(y);
        }
    }
}

// =====================================================================
// coalesced weight packing (fp16, pair-packed uint4 fragments)
// =====================================================================
#define TP1 260
__global__ __launch_bounds__(256) void k_packw1(const float* __restrict__ K1)
{
    __shared__ float tile[16 * TP1];
    int tap = blockIdx.x, chunk = blockIdx.y, c = blockIdx.z;
    int t = threadIdx.x;
    const float* src = K1 + (((size_t)c * 25 + tap) * 306 + chunk * 16) * 256;
    for (int idx = t; idx < 1024; idx += 256) {
        int r = idx >> 6, c4 = idx & 63;
        *(float4*)&tile[r * TP1 + c4 * 4] = ((const float4*)src)[idx];
    }
    __syncthreads();
    int lane = t & 31, wp = t >> 5;
    int k0 = (lane & 3) * 2, nq = lane >> 2;
    for (int ntp = wp; ntp < 16; ntp += 8) {
        int nA = ntp * 16 + nq;
        int nB = nA + 8;
        uint4 o;
        o.x = h2pack(tile[(k0 + 0) * TP1 + nA], tile[(k0 + 1) * TP1 + nA]);
        o.y = h2pack(tile[(k0 + 8) * TP1 + nA], tile[(k0 + 9) * TP1 + nA]);
        o.z = h2pack(tile[(k0 + 0) * TP1 + nB], tile[(k0 + 1) * TP1 + nB]);
        o.w = h2pack(tile[(k0 + 8) * TP1 + nB], tile[(k0 + 9) * TP1 + nB]);
        g_W1[((((size_t)c * 16 + chunk) * 25 + tap) * 16 + ntp) * 32 + lane] = o;
    }
}

#define TP2 132
__global__ __launch_bounds__(256) void k_packw2(const float* __restrict__ K2)
{
    __shared__ float tile[16 * TP2];
    int tap = blockIdx.x, chunk = blockIdx.y, c = blockIdx.z;
    int t = threadIdx.x;
    const float* src = K2 + (((size_t)c * 25 + tap) * 256 + chunk * 16) * 128;
    for (int idx = t; idx < 512; idx += 256) {
        int r = idx >> 5, c4 = idx & 31;
        *(float4*)&tile[r * TP2 + c4 * 4] = ((const float4*)src)[idx];
    }
    __syncthreads();
    int lane = t & 31, wp = t >> 5;
    int k0 = (lane & 3) * 2, nq = lane >> 2;
    if (wp < 8) {
        int ntp = wp;
        int nA = ntp * 16 + nq;
        int nB = nA + 8;
        uint4 o;
        o.x = h2pack(tile[(k0 + 0) * TP2 + nA], tile[(k0 + 1) * TP2 + nA]);
        o.y = h2pack(tile[(k0 + 8) * TP2 + nA], tile[(k0 + 9) * TP2 + nA]);
        o.z = h2pack(tile[(k0 + 0) * TP2 + nB], tile[(k0 + 1) * TP2 + nB]);
        o.w = h2pack(tile[(k0 + 8) * TP2 + nB], tile[(k0 + 9) * TP2 + nB]);
        g_W2[((((size_t)c * 16 + chunk) * 25 + tap) * 8 + ntp) * 32 + lane] = o;
    }
}

// =====================================================================
// emb fold
// =====================================================================
__global__ __launch_bounds__(256) void k_embw(
    const float* __restrict__ K1, const float* __restrict__ emb)
{
    __shared__ float es[EMBD];
    int tap = blockIdx.x, c = blockIdx.y, t = threadIdx.x;
    if (t < EMBD) es[t] = emb[c * EMBD + t];
    __syncthreads();
    const float* kb = K1 + (((size_t)c * 25 + tap) * 306 + 256) * 256 + t;
    float acc = 0.f;
#pragma unroll 10
    for (int e = 0; e < EMBD; e++) acc += es[e] * kb[(size_t)e * 256];
    g_embw[((size_t)c * 25 + tap) * 256 + t] = acc;
}

__global__ __launch_bounds__(256) void k_embe(const float* dummy)
{
    int p = blockIdx.x, c = blockIdx.y, t = threadIdx.x;
    int i = p / 7, j = p - 7 * i;
    float acc = 0.f;
    for (int di = 0; di < 5; di++) {
        int ii = i + di - 2; if ((unsigned)ii >= 7u) continue;
        for (int dj = 0; dj < 5; dj++) {
            int jj = j + dj - 2; if ((unsigned)jj >= 7u) continue;
            acc += g_embw[((size_t)c * 25 + di * 5 + dj) * 256 + t];
        }
    }
    g_embf[((size_t)c * 49 + p) * 256 + t] = acc;
}

// =====================================================================
// conv1: implicit GEMM, 4 samples/CTA, 64 co, 7 warps.
// Double-buffered A tiles (cp.async) + pair-packed LDG.128 weights.
// =====================================================================
#define SPL1   2960
#define A1_FP  (4 * SPL1)
#define A1_B   (A1_FP * 2)             // 23680 bytes per buffer

__global__ __launch_bounds__(224, 2) void k_conv1(
    const float* __restrict__ G1, const float* __restrict__ B1,
    const float* __restrict__ M1, const float* __restrict__ V1)
{
    extern __shared__ __align__(16) char smraw[];
    __half* A = (__half*)smraw;            // 2 buffers of A1_B

    const int c = blockIdx.z;
    const int n_c = g_cnt[c];
    const int stile = blockIdx.x;
    if (stile * 4 >= n_c) return;
    const int by = blockIdx.y;
    const int co0 = by * 64;
    const int t = threadIdx.x, lane = t & 31, wrp = t >> 5;
    const int base = g_off[c];

    int samp[4]; bool sok[4];
#pragma unroll
    for (int s = 0; s < 4; s++) {
        int idx = stile * 4 + s;
        sok[s] = idx < n_c;
        samp[s] = g_perm[base + (idx < n_c ? idx : n_c - 1)];
    }

    const uint32_t a_u32 = (uint32_t)__cvta_generic_to_shared(A);
    const int lm = lane & 15;
    const int ljx = lm >> 2, ls = lm & 3;
    const int koff = (lane >> 4) * 8;
    const uint32_t lb0 = a_u32 + (uint32_t)((ls * SPL1 + ljx * 24 + koff) * 2);
    const uint32_t lb1 = a_u32 + (uint32_t)((ls * SPL1 + (ljx + 4) * 24 + koff) * 2);

    // refill thread-local precompute
    int rs = 0, rpos = 0; const __half* rsrc0 = nullptr;
    if (t < 196) {
        rs = t / 49; int p = t - rs * 49;
        int pi_ = p / 7, pj_ = p - 7 * pi_;
        rpos = (rs * SPL1 + ((2 + pi_) * 11 + 2 + pj_) * 24) * 2;
        rsrc0 = g_a0 + ((size_t)samp[rs] * 49 + p) * 256;
    }

    for (int q = t; q < 2 * A1_FP / 8; q += 224) ((uint4*)A)[q] = make_uint4(0, 0, 0, 0);
    __syncthreads();

    float acc[2][8][4];
#pragma unroll
    for (int mb = 0; mb < 2; mb++)
#pragma unroll
        for (int nt = 0; nt < 8; nt++)
#pragma unroll
            for (int u = 0; u < 4; u++) acc[mb][nt][u] = 0.f;

    const uint4* wbase = g_W1 + ((size_t)c * 16 * 25 * 16 + (size_t)by * 4) * 32 + lane;

    // prologue: async-load chunk 0 into buffer 0
    if (t < 196) {
        uint32_t d = a_u32 + (uint32_t)rpos;
        cp16(d, rsrc0); cp16(d + 16, rsrc0 + 8);
    }
    CP_COMMIT();

    for (int chunk = 0; chunk < 16; chunk++) {
        CP_WAIT0();
        __syncthreads();
        if (chunk + 1 < 16) {
            if (t < 196) {
                uint32_t d = a_u32 + (uint32_t)(((chunk + 1) & 1) * A1_B) + (uint32_t)rpos;
                const __half* src = rsrc0 + (chunk + 1) * 16;
                cp16(d, src); cp16(d + 16, src + 8);
            }
            CP_COMMIT();
        }
        const uint32_t bufo = (uint32_t)((chunk & 1) * A1_B);

        const uint4* wch = wbase + (size_t)chunk * 25 * 16 * 32;
#pragma unroll
        for (int di = 0; di < 5; di++) {
#pragma unroll
            for (int dj = 0; dj < 5; dj++) {
                const uint32_t goff = bufo + (uint32_t)(((wrp + di) * 11 + dj) * 48);
                uint32_t a0[4], a1[4];
                LDSM4(a0, lb0 + goff);
                LDSM4(a1, lb1 + goff);
                const uint4* wt = wch + (di * 5 + dj) * (16 * 32);
                uint4 bf[4];
#pragma unroll
                for (int p = 0; p < 4; p++) bf[p] = __ldg(wt + p * 32);
#pragma unroll
                for (int p = 0; p < 4; p++) {
                    MMA2(acc[0][2 * p + 0], a0, bf[p].x, bf[p].y);
                    MMA2(acc[1][2 * p + 0], a1, bf[p].x, bf[p].y);
                    MMA2(acc[0][2 * p + 1], a0, bf[p].z, bf[p].w);
                    MMA2(acc[1][2 * p + 1], a1, bf[p].z, bf[p].w);
                }
            }
        }
    }

    // epilogue: + E, BN, LReLU -> act1 fp16
    const int g_ = lane >> 2;
    const int n_ = (lane & 3) * 2;
#pragma unroll
    for (int mb = 0; mb < 2; mb++) {
#pragma unroll
        for (int nt = 0; nt < 8; nt++) {
            int co = co0 + nt * 8 + n_;
            float2 gg = *(const float2*)(G1 + c * 256 + co);
            float2 bb = *(const float2*)(B1 + c * 256 + co);
            float2 mm = *(const float2*)(M1 + c * 256 + co);
            float2 vv = *(const float2*)(V1 + c * 256 + co);
            float sx = rsqrtf(vv.x + 1e-3f) * gg.x;
            float sy = rsqrtf(vv.y + 1e-3f) * gg.y;
#pragma unroll
            for (int h = 0; h < 2; h++) {
                int m = mb * 16 + g_ + h * 8;
                int jx = m >> 2, s = m & 3;
                if (jx < 7 && sok[s]) {
                    int pos = wrp * 7 + jx;
                    float2 E = *(const float2*)(g_embf + ((size_t)c * 49 + pos) * 256 + co);
                    float y0 = lrelu((acc[mb][nt][h * 2 + 0] + E.x - mm.x) * sx + bb.x);
                    float y1 = lrelu((acc[mb][nt][h * 2 + 1] + E.y - mm.y) * sy + bb.y);
                    *(__half2*)(g_a1 + ((size_t)samp[s] * 49 + pos) * 256 + co) =
                        __halves2half2(__float2half(y0), __float2half(y1));
                }
            }
        }
    }
}

// =====================================================================
// conv2: parity-decomposed implicit GEMM, 4 samples/CTA, 64 co.
// Double-buffered A tiles (cp.async) + pair-packed LDG.128 weights.
// =====================================================================
#define SPL2   2000
#define A2_FP  (4 * SPL2)
#define A2_B   (A2_FP * 2)             // 16000 bytes per buffer

__global__ __launch_bounds__(224, 2) void k_conv2(
    const float* __restrict__ G2, const float* __restrict__ B2,
    const float* __restrict__ M2, const float* __restrict__ V2)
{
    extern __shared__ __align__(16) char smraw[];
    __half* A = (__half*)smraw;            // 2 buffers of A2_B

    const int c = blockIdx.z;
    const int n_c = g_cnt[c];
    const int stile = blockIdx.x;
    if (stile * 4 >= n_c) return;
    const int by = blockIdx.y;
    const int co0 = by * 64;
    const int t = threadIdx.x, lane = t & 31, wrp = t >> 5;
    const int base = g_off[c];

    int samp[4]; bool sok[4];
#pragma unroll
    for (int s = 0; s < 4; s++) {
        int idx = stile * 4 + s;
        sok[s] = idx < n_c;
        samp[s] = g_perm[base + (idx < n_c ? idx : n_c - 1)];
    }

    const uint32_t a_u32 = (uint32_t)__cvta_generic_to_shared(A);
    const int lm = lane & 15;
    const int ljx = lm >> 2, ls = lm & 3;
    const int koff = (lane >> 4) * 8;
    const uint32_t lb0 = a_u32 + (uint32_t)((ls * SPL2 + ljx * 24 + koff) * 2);
    const uint32_t lb1 = a_u32 + (uint32_t)((ls * SPL2 + (ljx + 4) * 24 + koff) * 2);

    int rpos = 0; const __half* rsrc0 = nullptr;
    if (t < 196) {
        int rs = t / 49; int p = t - rs * 49;
        int pi_ = p / 7, pj_ = p - 7 * pi_;
        rpos = (rs * SPL2 + ((1 + pi_) * 9 + 1 + pj_) * 24) * 2;
        rsrc0 = g_a1 + ((size_t)samp[rs] * 49 + p) * 256;
    }

    for (int q = t; q < 2 * A2_FP / 8; q += 224) ((uint4*)A)[q] = make_uint4(0, 0, 0, 0);
    __syncthreads();

    const uint4* wcls = g_W2 + ((size_t)c * 16 * 25 * 8 + (size_t)by * 4) * 32 + lane;
    const int g_ = lane >> 2;
    const int n_ = (lane & 3) * 2;

    for (int pp = 0; pp < 4; pp++) {
        const int pi = pp >> 1, pj = pp & 1;
        const int ni = (pi == 0) ? 2 : 3, nj = (pj == 0) ? 2 : 3;

        float acc[2][8][4];
#pragma unroll
        for (int mb = 0; mb < 2; mb++)
#pragma unroll
            for (int nt = 0; nt < 8; nt++)
#pragma unroll
                for (int u = 0; u < 4; u++) acc[mb][nt][u] = 0.f;

        // prologue: async-load chunk 0 into buffer 0 (prev pass's chunk14 compute
        // finished before its chunk15 top-barrier -> buffer 0 free)
        if (t < 196) {
            uint32_t d = a_u32 + (uint32_t)rpos;
            cp16(d, rsrc0); cp16(d + 16, rsrc0 + 8);
        }
        CP_COMMIT();

        for (int chunk = 0; chunk < 16; chunk++) {
            CP_WAIT0();
            __syncthreads();
            if (chunk + 1 < 16) {
                if (t < 196) {
                    uint32_t d = a_u32 + (uint32_t)(((chunk + 1) & 1) * A2_B) + (uint32_t)rpos;
                    const __half* src = rsrc0 + (chunk + 1) * 16;
                    cp16(d, src); cp16(d + 16, src + 8);
                }
                CP_COMMIT();
            }
            const uint32_t bufo = (uint32_t)((chunk & 1) * A2_B);

            const uint4* wch = wcls + (size_t)chunk * 25 * 8 * 32;
            for (int ui = 0; ui < ni; ui++) {
                int ddi = (pi == 0) ? (1 + 2 * ui) : (2 * ui);
                int si = (ddi >> 1) - 1;
                for (int uj = 0; uj < nj; uj++) {
                    int ddj = (pj == 0) ? (1 + 2 * uj) : (2 * uj);
                    int sj = (ddj >> 1) - 1;
                    const uint32_t goff = bufo + (uint32_t)(((1 + wrp + si) * 9 + 1 + sj) * 48);
                    uint32_t a0[4], a1[4];
                    LDSM4(a0, lb0 + goff);
                    LDSM4(a1, lb1 + goff);
                    const uint4* wt = wch + (ddi * 5 + ddj) * (8 * 32);
                    uint4 bf[4];
#pragma unroll
                    for (int p = 0; p < 4; p++) bf[p] = __ldg(wt + p * 32);
#pragma unroll
                    for (int p = 0; p < 4; p++) {
                        MMA2(acc[0][2 * p + 0], a0, bf[p].x, bf[p].y);
                        MMA2(acc[1][2 * p + 0], a1, bf[p].x, bf[p].y);
                        MMA2(acc[0][2 * p + 1], a0, bf[p].z, bf[p].w);
                        MMA2(acc[1][2 * p + 1], a1, bf[p].z, bf[p].w);
                    }
                }
            }
        }

        // epilogue this parity -> act2 fp16
#pragma unroll
        for (int mb = 0; mb < 2; mb++) {
#pragma unroll
            for (int nt = 0; nt < 8; nt++) {
                int co = co0 + nt * 8 + n_;
                float2 gg = *(const float2*)(G2 + c * 128 + co);
                float2 bb = *(const float2*)(B2 + c * 128 + co);
                float2 mm = *(const float2*)(M2 + c * 128 + co);
                float2 vv = *(const float2*)(V2 + c * 128 + co);
                float sx = rsqrtf(vv.x + 1e-3f) * gg.x;
                float sy = rsqrtf(vv.y + 1e-3f) * gg.y;
#pragma unroll
                for (int h = 0; h < 2; h++) {
                    int m = mb * 16 + g_ + h * 8;
                    int jx = m >> 2, s = m & 3;
                    if (jx < 7 && sok[s]) {
                        int oi = 2 * wrp + pi, oj = 2 * jx + pj;
                        float y0 = lrelu((acc[mb][nt][h * 2 + 0] - mm.x) * sx + bb.x);
                        float y1 = lrelu((acc[mb][nt][h * 2 + 1] - mm.y) * sy + bb.y);
                        *(__half2*)(g_a2 + ((size_t)samp[s] * 196 + oi * 14 + oj) * 128 + co) =
                            __halves2half2(__float2half(y0), __float2half(y1));
                    }
                }
            }
        }
    }
}

// =====================================================================
// conv3: 5x5 s2, 128 -> 1, tanh (fp16 inputs)
// =====================================================================
#define D_IN_B (196 * C2 * 2)          // 50176 bytes
#define D_W_B  (25 * C2 * 4)           // 12800 bytes

__global__ __launch_bounds__(256, 2) void k_conv3(
    const int* __restrict__ labels, const float* __restrict__ K3,
    float* __restrict__ out)
{
    extern __shared__ __align__(16) char smraw[];
    __half* in_h = (__half*)smraw;
    float*  w_s  = (float*)(smraw + D_IN_B);
    const int b = blockIdx.x;
    const int t = threadIdx.x;
    const int c = labels[b];

    const uint4* a2 = (const uint4*)(g_a2 + (size_t)b * (196 * C2));
    for (int q = t; q < 196 * 16; q += 256) ((uint4*)in_h)[q] = a2[q];
    const float4* k4 = (const float4*)(K3 + (size_t)c * 25 * C2);
    for (int q = t; q < 25 * 32; q += 256) ((float4*)w_s)[q] = k4[q];
    __syncthreads();

    for (int px = t; px < 784; px += 256) {
        const int oi = px / 28, oj = px - oi * 28;
        float acc = 0.f;
        for (int ddi = (oi & 1) ? 0 : 1; ddi < 5; ddi += 2) {
            int ii = (oi + ddi - 3) >> 1;
            if ((unsigned)ii >= 14u) continue;
            for (int ddj = (oj & 1) ? 0 : 1; ddj < 5; ddj += 2) {
                int jj = (oj + ddj - 3) >> 1;
                if ((unsigned)jj >= 14u) continue;
                const __half2* ip = (const __half2*)(in_h + (ii * 14 + jj) * C2);
                const float2* wp = (const float2*)(w_s + (ddi * 5 + ddj) * C2);
#pragma unroll 16
                for (int q = 0; q < 64; q++) {
                    float2 a = __half22float2(ip[q]);
                    float2 w = wp[q];
                    acc += a.x * w.x + a.y * w.y;
                }
            }
        }
        out[(size_t)b * 784 + px] = tanhf(acc);
    }
}

// =====================================================================
extern "C" void kernel_launch(void* const* d_in, const int* in_sizes, int n_in,
                              void* d_out, int out_size)
{
    const float* noise = (const float*)d_in[0];
    const int*   labels= (const int*)  d_in[1];
    const float* emb   = (const float*)d_in[2];
    const float* Wd    = (const float*)d_in[3];
    const float* bn1g  = (const float*)d_in[4];
    const float* bn1b  = (const float*)d_in[5];
    const float* bn1m  = (const float*)d_in[6];
    const float* bn1v  = (const float*)d_in[7];
    const float* K1    = (const float*)d_in[8];
    const float* G1    = (const float*)d_in[9];
    const float* B1    = (const float*)d_in[10];
    const float* M1    = (const float*)d_in[11];
    const float* V1    = (const float*)d_in[12];
    const float* K2    = (const float*)d_in[13];
    const float* G2    = (const float*)d_in[14];
    const float* B2    = (const float*)d_in[15];
    const float* M2    = (const float*)d_in[16];
    const float* V2    = (const float*)d_in[17];
    const float* K3    = (const float*)d_in[18];
    float* out = (float*)d_out;

    const int smB = 2 * A1_B;             // 47360
    const int smC = 2 * A2_B;             // 32000
    const int smD = D_IN_B + D_W_B;       // 62976
    cudaFuncSetAttribute(k_conv1, cudaFuncAttributeMaxDynamicSharedMemorySize, smB);
    cudaFuncSetAttribute(k_conv2, cudaFuncAttributeMaxDynamicSharedMemorySize, smC);
    cudaFuncSetAttribute(k_conv3, cudaFuncAttributeMaxDynamicSharedMemorySize, smD);

    k_dense<<<dim3(49, 64), 256>>>(noise, labels, emb, Wd, bn1g, bn1b, bn1m, bn1v);
    k_bucket<<<1, 512>>>(labels);
    k_packw1<<<dim3(25, 16, 10), 256>>>(K1);
    k_embw<<<dim3(25, 10), 256>>>(K1, emb);
    k_embe<<<dim3(49, 10), 256>>>(nullptr);
    k_conv1<<<dim3(32, 4, 10), 224, smB>>>(G1, B1, M1, V1);
    k_packw2<<<dim3(25, 16, 10), 256>>>(K2);
    k_conv2<<<dim3(32, 2, 10), 224, smC>>>(G2, B2, M2, V2);
    k_conv3<<<BATCH, 256, smD>>>(labels, K3, out);
}

// round 16
// speedup vs baseline: 1.0314x; 1.0314x over previous
#include <cuda_runtime.h>
#include <cuda_fp16.h>
#include <cstdint>

#define BATCH 512
#define NOISE 100
#define EMBD  50
#define NCLS  10
#define C1    256
#define C2    128

typedef unsigned long long ull;

// ---------------- scratch ----------------
__device__ __align__(16) __half g_a0[BATCH * 49 * 256];
__device__ __align__(16) __half g_a1[BATCH * 49 * 256];
__device__ __align__(16) __half g_a2[BATCH * 196 * C2];
__device__ __align__(16) float  g_embf[NCLS * 49 * 256];
__device__ __align__(16) float  g_embw[NCLS * 25 * 256];
// pair-packed weight fragments: uint4 = {frag(nt=2p) , frag(nt=2p+1)} per lane
__device__ __align__(16) uint4  g_W1[(size_t)NCLS * 16 * 25 * 16 * 32];
__device__ __align__(16) uint4  g_W2[(size_t)NCLS * 16 * 25 * 8 * 32];
__device__ __align__(16) uint4  g_Wd[(size_t)10 * 98 * 8 * 32];    // dense: K=160 (10 chunks), N=12544 (98 cb)
__device__ int g_perm[BATCH];
__device__ int g_cnt[NCLS];
__device__ int g_off[NCLS];

__device__ __forceinline__ float lrelu(float x) { return x >= 0.f ? x : 0.3f * x; }

#define LDSM4(a, addr) asm volatile( \
    "ldmatrix.sync.aligned.m8n8.x4.shared.b16 {%0,%1,%2,%3}, [%4];" \
    : "=r"(a[0]), "=r"(a[1]), "=r"(a[2]), "=r"(a[3]) : "r"(addr))

#define MMA2(d, a, bx_, by_) asm volatile( \
    "mma.sync.aligned.m16n8k16.row.col.f32.f16.f16.f32 " \
    "{%0,%1,%2,%3}, {%4,%5,%6,%7}, {%8,%9}, {%0,%1,%2,%3};" \
    : "+f"(d[0]), "+f"(d[1]), "+f"(d[2]), "+f"(d[3]) \
    : "r"(a[0]), "r"(a[1]), "r"(a[2]), "r"(a[3]), "r"(bx_), "r"(by_))

#define CP_COMMIT() asm volatile("cp.async.commit_group;" ::: "memory")
#define CP_WAIT0()  asm volatile("cp.async.wait_group 0;" ::: "memory")

__device__ __forceinline__ void cp16(uint32_t saddr, const void* g) {
    asm volatile("cp.async.cg.shared.global [%0], [%1], 16;" :: "r"(saddr), "l"(g) : "memory");
}

__device__ __forceinline__ uint32_t h2pack(float a, float b) {
    __half2 p = __halves2half2(__float2half(a), __float2half(b));
    return *(uint32_t*)&p;
}

// =====================================================================
__global__ __launch_bounds__(512) void k_bucket(const int* __restrict__ labels)
{
    __shared__ int scnt[NCLS], scur[NCLS];
    int t = threadIdx.x;
    if (t < NCLS) scnt[t] = 0;
    __syncthreads();
    int c = labels[t];
    atomicAdd(&scnt[c], 1);
    __syncthreads();
    if (t == 0) {
        int run = 0;
        for (int k = 0; k < NCLS; k++) { g_off[k] = run; scur[k] = run; g_cnt[k] = scnt[k]; run += scnt[k]; }
    }
    __syncthreads();
    int pos = atomicAdd(&scur[c], 1);
    g_perm[pos] = t;
}

// =====================================================================
// dense weight pack: Wd [150(pad160) x 12544] -> pair-packed b-fragments
// =====================================================================
#define TPD 132
__global__ __launch_bounds__(256) void k_packwd(const float* __restrict__ Wd)
{
    __shared__ float tile[16 * TPD];
    int cb = blockIdx.x, ch = blockIdx.y;
    int t = threadIdx.x;
    for (int idx = t; idx < 512; idx += 256) {
        int r = idx >> 5, c4 = idx & 31;
        int k = ch * 16 + r;
        float4 v = make_float4(0.f, 0.f, 0.f, 0.f);
        if (k < 150) v = *(const float4*)(Wd + (size_t)k * 12544 + cb * 128 + c4 * 4);
        *(float4*)&tile[r * TPD + c4 * 4] = v;
    }
    __syncthreads();
    int lane = t & 31, wp = t >> 5;
    int k0 = (lane & 3) * 2, nq = lane >> 2;
    if (wp < 8) {
        int ntp = wp;
        int nA = ntp * 16 + nq;
        int nB = nA + 8;
        uint4 o;
        o.x = h2pack(tile[(k0 + 0) * TPD + nA], tile[(k0 + 1) * TPD + nA]);
        o.y = h2pack(tile[(k0 + 8) * TPD + nA], tile[(k0 + 9) * TPD + nA]);
        o.z = h2pack(tile[(k0 + 0) * TPD + nB], tile[(k0 + 1) * TPD + nB]);
        o.w = h2pack(tile[(k0 + 8) * TPD + nB], tile[(k0 + 9) * TPD + nB]);
        g_Wd[((size_t)(ch * 98 + cb) * 8 + ntp) * 32 + lane] = o;
    }
}

// =====================================================================
// dense on tensor cores: out[512, 12544] = x[512,160] @ Wd ; BN ; LReLU
// CTA: 16 samples x 128 features, 4 warps (1 mtile, 4 ntiles/warp)
// =====================================================================
__global__ __launch_bounds__(128) void k_dense2(
    const float* __restrict__ noise, const int* __restrict__ labels,
    const float* __restrict__ emb,
    const float* __restrict__ bn_g,  const float* __restrict__ bn_b,
    const float* __restrict__ bn_m,  const float* __restrict__ bn_v)
{
    __shared__ __align__(16) __half xs[10 * 16 * 24];   // [chunk][sample][pitch24]
    const int t = threadIdx.x;
    const int cb = blockIdx.x;
    const int b0 = blockIdx.y * 16;
    const int lane = t & 31, w = t >> 5;

    for (int idx = t; idx < 16 * 160; idx += 128) {
        int s = idx / 160, k = idx - s * 160;
        float val = 0.f;
        if (k < NOISE) val = noise[(b0 + s) * NOISE + k];
        else if (k < 150) val = emb[labels[b0 + s] * EMBD + (k - NOISE)];
        int ch = k >> 4, kl = k & 15;
        xs[(ch * 16 + s) * 24 + kl] = __float2half(val);
    }
    __syncthreads();

    const uint32_t a_u32 = (uint32_t)__cvta_generic_to_shared(xs);
    const int lm = lane & 15;
    const int koff = (lane >> 4) * 8;
    const uint32_t lb = a_u32 + (uint32_t)((lm * 24 + koff) * 2);

    float acc[4][4];
#pragma unroll
    for (int a = 0; a < 4; a++)
#pragma unroll
        for (int u = 0; u < 4; u++) acc[a][u] = 0.f;

#pragma unroll
    for (int ch = 0; ch < 10; ch++) {
        uint32_t a[4];
        LDSM4(a, lb + (uint32_t)(ch * 768));
#pragma unroll
        for (int pp = 0; pp < 2; pp++) {
            int ntp = w * 2 + pp;
            uint4 bf = __ldg(&g_Wd[((size_t)(ch * 98 + cb) * 8 + ntp) * 32 + lane]);
            MMA2(acc[pp * 2 + 0], a, bf.x, bf.y);
            MMA2(acc[pp * 2 + 1], a, bf.z, bf.w);
        }
    }

    const int g_ = lane >> 2;
    const int n_ = (lane & 3) * 2;
#pragma unroll
    for (int pp = 0; pp < 2; pp++) {
#pragma unroll
        for (int q = 0; q < 2; q++) {
            int aidx = pp * 2 + q;
            int j0 = cb * 128 + (w * 2 + pp) * 16 + q * 8 + n_;
            float2 gg = *(const float2*)(bn_g + j0);
            float2 bb = *(const float2*)(bn_b + j0);
            float2 mm = *(const float2*)(bn_m + j0);
            float2 vv = *(const float2*)(bn_v + j0);
            float sx = rsqrtf(vv.x + 1e-3f) * gg.x;
            float sy = rsqrtf(vv.y + 1e-3f) * gg.y;
#pragma unroll
            for (int h = 0; h < 2; h++) {
                int m = g_ + h * 8;
                float y0 = lrelu((acc[aidx][h * 2 + 0] - mm.x) * sx + bb.x);
                float y1 = lrelu((acc[aidx][h * 2 + 1] - mm.y) * sy + bb.y);
                *(__half2*)(g_a0 + (size_t)(b0 + m) * 12544 + j0) =
                    __halves2half2(__float2half(y0), __float2half(y1));
            }
        }
    }
}

// =====================================================================
// conv weight packing (fp16, pair-packed uint4 fragments)
// =====================================================================
#define TP1 260
__global__ __launch_bounds__(256) void k_packw1(const float* __restrict__ K1)
{
    __shared__ float tile[16 * TP1];
    int tap = blockIdx.x, chunk = blockIdx.y, c = blockIdx.z;
    int t = threadIdx.x;
    const float* src = K1 + (((size_t)c * 25 + tap) * 306 + chunk * 16) * 256;
    for (int idx = t; idx < 1024; idx += 256) {
        int r = idx >> 6, c4 = idx & 63;
        *(float4*)&tile[r * TP1 + c4 * 4] = ((const float4*)src)[idx];
    }
    __syncthreads();
    int lane = t & 31, wp = t >> 5;
    int k0 = (lane & 3) * 2, nq = lane >> 2;
    for (int ntp = wp; ntp < 16; ntp += 8) {
        int nA = ntp * 16 + nq;
        int nB = nA + 8;
        uint4 o;
        o.x = h2pack(tile[(k0 + 0) * TP1 + nA], tile[(k0 + 1) * TP1 + nA]);
        o.y = h2pack(tile[(k0 + 8) * TP1 + nA], tile[(k0 + 9) * TP1 + nA]);
        o.z = h2pack(tile[(k0 + 0) * TP1 + nB], tile[(k0 + 1) * TP1 + nB]);
        o.w = h2pack(tile[(k0 + 8) * TP1 + nB], tile[(k0 + 9) * TP1 + nB]);
        g_W1[((((size_t)c * 16 + chunk) * 25 + tap) * 16 + ntp) * 32 + lane] = o;
    }
}

#define TP2 132
__global__ __launch_bounds__(256) void k_packw2(const float* __restrict__ K2)
{
    __shared__ float tile[16 * TP2];
    int tap = blockIdx.x, chunk = blockIdx.y, c = blockIdx.z;
    int t = threadIdx.x;
    const float* src = K2 + (((size_t)c * 25 + tap) * 256 + chunk * 16) * 128;
    for (int idx = t; idx < 512; idx += 256) {
        int r = idx >> 5, c4 = idx & 31;
        *(float4*)&tile[r * TP2 + c4 * 4] = ((const float4*)src)[idx];
    }
    __syncthreads();
    int lane = t & 31, wp = t >> 5;
    int k0 = (lane & 3) * 2, nq = lane >> 2;
    if (wp < 8) {
        int ntp = wp;
        int nA = ntp * 16 + nq;
        int nB = nA + 8;
        uint4 o;
        o.x = h2pack(tile[(k0 + 0) * TP2 + nA], tile[(k0 + 1) * TP2 + nA]);
        o.y = h2pack(tile[(k0 + 8) * TP2 + nA], tile[(k0 + 9) * TP2 + nA]);
        o.z = h2pack(tile[(k0 + 0) * TP2 + nB], tile[(k0 + 1) * TP2 + nB]);
        o.w = h2pack(tile[(k0 + 8) * TP2 + nB], tile[(k0 + 9) * TP2 + nB]);
        g_W2[((((size_t)c * 16 + chunk) * 25 + tap) * 8 + ntp) * 32 + lane] = o;
    }
}

// =====================================================================
// emb fold
// =====================================================================
__global__ __launch_bounds__(256) void k_embw(
    const float* __restrict__ K1, const float* __restrict__ emb)
{
    __shared__ float es[EMBD];
    int tap = blockIdx.x, c = blockIdx.y, t = threadIdx.x;
    if (t < EMBD) es[t] = emb[c * EMBD + t];
    __syncthreads();
    const float* kb = K1 + (((size_t)c * 25 + tap) * 306 + 256) * 256 + t;
    float acc = 0.f;
#pragma unroll 10
    for (int e = 0; e < EMBD; e++) acc += es[e] * kb[(size_t)e * 256];
    g_embw[((size_t)c * 25 + tap) * 256 + t] = acc;
}

__global__ __launch_bounds__(256) void k_embe(const float* dummy)
{
    int p = blockIdx.x, c = blockIdx.y, t = threadIdx.x;
    int i = p / 7, j = p - 7 * i;
    float acc = 0.f;
    for (int di = 0; di < 5; di++) {
        int ii = i + di - 2; if ((unsigned)ii >= 7u) continue;
        for (int dj = 0; dj < 5; dj++) {
            int jj = j + dj - 2; if ((unsigned)jj >= 7u) continue;
            acc += g_embw[((size_t)c * 25 + di * 5 + dj) * 256 + t];
        }
    }
    g_embf[((size_t)c * 49 + p) * 256 + t] = acc;
}

// =====================================================================
// conv1: implicit GEMM, 4 samples/CTA, 64 co, 7 warps.
// Double-buffered A tiles (cp.async) + pair-packed LDG.128 weights.
// =====================================================================
#define SPL1   2960
#define A1_FP  (4 * SPL1)
#define A1_B   (A1_FP * 2)

__global__ __launch_bounds__(224, 2) void k_conv1(
    const float* __restrict__ G1, const float* __restrict__ B1,
    const float* __restrict__ M1, const float* __restrict__ V1)
{
    extern __shared__ __align__(16) char smraw[];
    __half* A = (__half*)smraw;

    const int c = blockIdx.z;
    const int n_c = g_cnt[c];
    const int stile = blockIdx.x;
    if (stile * 4 >= n_c) return;
    const int by = blockIdx.y;
    const int co0 = by * 64;
    const int t = threadIdx.x, lane = t & 31, wrp = t >> 5;
    const int base = g_off[c];

    int samp[4]; bool sok[4];
#pragma unroll
    for (int s = 0; s < 4; s++) {
        int idx = stile * 4 + s;
        sok[s] = idx < n_c;
        samp[s] = g_perm[base + (idx < n_c ? idx : n_c - 1)];
    }

    const uint32_t a_u32 = (uint32_t)__cvta_generic_to_shared(A);
    const int lm = lane & 15;
    const int ljx = lm >> 2, ls = lm & 3;
    const int koff = (lane >> 4) * 8;
    const uint32_t lb0 = a_u32 + (uint32_t)((ls * SPL1 + ljx * 24 + koff) * 2);
    const uint32_t lb1 = a_u32 + (uint32_t)((ls * SPL1 + (ljx + 4) * 24 + koff) * 2);

    int rpos = 0; const __half* rsrc0 = nullptr;
    if (t < 196) {
        int rs = t / 49; int p = t - rs * 49;
        int pi_ = p / 7, pj_ = p - 7 * pi_;
        rpos = (rs * SPL1 + ((2 + pi_) * 11 + 2 + pj_) * 24) * 2;
        rsrc0 = g_a0 + ((size_t)samp[rs] * 49 + p) * 256;
    }

    for (int q = t; q < 2 * A1_FP / 8; q += 224) ((uint4*)A)[q] = make_uint4(0, 0, 0, 0);
    __syncthreads();

    float acc[2][8][4];
#pragma unroll
    for (int mb = 0; mb < 2; mb++)
#pragma unroll
        for (int nt = 0; nt < 8; nt++)
#pragma unroll
            for (int u = 0; u < 4; u++) acc[mb][nt][u] = 0.f;

    const uint4* wbase = g_W1 + ((size_t)c * 16 * 25 * 16 + (size_t)by * 4) * 32 + lane;

    if (t < 196) {
        uint32_t d = a_u32 + (uint32_t)rpos;
        cp16(d, rsrc0); cp16(d + 16, rsrc0 + 8);
    }
    CP_COMMIT();

    for (int chunk = 0; chunk < 16; chunk++) {
        CP_WAIT0();
        __syncthreads();
        if (chunk + 1 < 16) {
            if (t < 196) {
                uint32_t d = a_u32 + (uint32_t)(((chunk + 1) & 1) * A1_B) + (uint32_t)rpos;
                const __half* src = rsrc0 + (chunk + 1) * 16;
                cp16(d, src); cp16(d + 16, src + 8);
            }
            CP_COMMIT();
        }
        const uint32_t bufo = (uint32_t)((chunk & 1) * A1_B);

        const uint4* wch = wbase + (size_t)chunk * 25 * 16 * 32;
#pragma unroll
        for (int di = 0; di < 5; di++) {
#pragma unroll
            for (int dj = 0; dj < 5; dj++) {
                const uint32_t goff = bufo + (uint32_t)(((wrp + di) * 11 + dj) * 48);
                uint32_t a0[4], a1[4];
                LDSM4(a0, lb0 + goff);
                LDSM4(a1, lb1 + goff);
                const uint4* wt = wch + (di * 5 + dj) * (16 * 32);
                uint4 bf[4];
#pragma unroll
                for (int p = 0; p < 4; p++) bf[p] = __ldg(wt + p * 32);
#pragma unroll
                for (int p = 0; p < 4; p++) {
                    MMA2(acc[0][2 * p + 0], a0, bf[p].x, bf[p].y);
                    MMA2(acc[1][2 * p + 0], a1, bf[p].x, bf[p].y);
                    MMA2(acc[0][2 * p + 1], a0, bf[p].z, bf[p].w);
                    MMA2(acc[1][2 * p + 1], a1, bf[p].z, bf[p].w);
                }
            }
        }
    }

    const int g_ = lane >> 2;
    const int n_ = (lane & 3) * 2;
#pragma unroll
    for (int mb = 0; mb < 2; mb++) {
#pragma unroll
        for (int nt = 0; nt < 8; nt++) {
            int co = co0 + nt * 8 + n_;
            float2 gg = *(const float2*)(G1 + c * 256 + co);
            float2 bb = *(const float2*)(B1 + c * 256 + co);
            float2 mm = *(const float2*)(M1 + c * 256 + co);
            float2 vv = *(const float2*)(V1 + c * 256 + co);
            float sx = rsqrtf(vv.x + 1e-3f) * gg.x;
            float sy = rsqrtf(vv.y + 1e-3f) * gg.y;
#pragma unroll
            for (int h = 0; h < 2; h++) {
                int m = mb * 16 + g_ + h * 8;
                int jx = m >> 2, s = m & 3;
                if (jx < 7 && sok[s]) {
                    int pos = wrp * 7 + jx;
                    float2 E = *(const float2*)(g_embf + ((size_t)c * 49 + pos) * 256 + co);
                    float y0 = lrelu((acc[mb][nt][h * 2 + 0] + E.x - mm.x) * sx + bb.x);
                    float y1 = lrelu((acc[mb][nt][h * 2 + 1] + E.y - mm.y) * sy + bb.y);
                    *(__half2*)(g_a1 + ((size_t)samp[s] * 49 + pos) * 256 + co) =
                        __halves2half2(__float2half(y0), __float2half(y1));
                }
            }
        }
    }
}

// =====================================================================
// conv2: parity-decomposed implicit GEMM, 4 samples/CTA, 64 co.
// =====================================================================
#define SPL2   2000
#define A2_FP  (4 * SPL2)
#define A2_B   (A2_FP * 2)

__global__ __launch_bounds__(224, 2) void k_conv2(
    const float* __restrict__ G2, const float* __restrict__ B2,
    const float* __restrict__ M2, const float* __restrict__ V2)
{
    extern __shared__ __align__(16) char smraw[];
    __half* A = (__half*)smraw;

    const int c = blockIdx.z;
    const int n_c = g_cnt[c];
    const int stile = blockIdx.x;
    if (stile * 4 >= n_c) return;
    const int by = blockIdx.y;
    const int co0 = by * 64;
    const int t = threadIdx.x, lane = t & 31, wrp = t >> 5;
    const int base = g_off[c];

    int samp[4]; bool sok[4];
#pragma unroll
    for (int s = 0; s < 4; s++) {
        int idx = stile * 4 + s;
        sok[s] = idx < n_c;
        samp[s] = g_perm[base + (idx < n_c ? idx : n_c - 1)];
    }

    const uint32_t a_u32 = (uint32_t)__cvta_generic_to_shared(A);
    const int lm = lane & 15;
    const int ljx = lm >> 2, ls = lm & 3;
    const int koff = (lane >> 4) * 8;
    const uint32_t lb0 = a_u32 + (uint32_t)((ls * SPL2 + ljx * 24 + koff) * 2);
    const uint32_t lb1 = a_u32 + (uint32_t)((ls * SPL2 + (ljx + 4) * 24 + koff) * 2);

    int rpos = 0; const __half* rsrc0 = nullptr;
    if (t < 196) {
        int rs = t / 49; int p = t - rs * 49;
        int pi_ = p / 7, pj_ = p - 7 * pi_;
        rpos = (rs * SPL2 + ((1 + pi_) * 9 + 1 + pj_) * 24) * 2;
        rsrc0 = g_a1 + ((size_t)samp[rs] * 49 + p) * 256;
    }

    for (int q = t; q < 2 * A2_FP / 8; q += 224) ((uint4*)A)[q] = make_uint4(0, 0, 0, 0);
    __syncthreads();

    const uint4* wcls = g_W2 + ((size_t)c * 16 * 25 * 8 + (size_t)by * 4) * 32 + lane;
    const int g_ = lane >> 2;
    const int n_ = (lane & 3) * 2;

    for (int pp = 0; pp < 4; pp++) {
        const int pi = pp >> 1, pj = pp & 1;
        const int ni = (pi == 0) ? 2 : 3, nj = (pj == 0) ? 2 : 3;

        float acc[2][8][4];
#pragma unroll
        for (int mb = 0; mb < 2; mb++)
#pragma unroll
            for (int nt = 0; nt < 8; nt++)
#pragma unroll
                for (int u = 0; u < 4; u++) acc[mb][nt][u] = 0.f;

        if (t < 196) {
            uint32_t d = a_u32 + (uint32_t)rpos;
            cp16(d, rsrc0); cp16(d + 16, rsrc0 + 8);
        }
        CP_COMMIT();

        for (int chunk = 0; chunk < 16; chunk++) {
            CP_WAIT0();
            __syncthreads();
            if (chunk + 1 < 16) {
                if (t < 196) {
                    uint32_t d = a_u32 + (uint32_t)(((chunk + 1) & 1) * A2_B) + (uint32_t)rpos;
                    const __half* src = rsrc0 + (chunk + 1) * 16;
                    cp16(d, src); cp16(d + 16, src + 8);
                }
                CP_COMMIT();
            }
            const uint32_t bufo = (uint32_t)((chunk & 1) * A2_B);

            const uint4* wch = wcls + (size_t)chunk * 25 * 8 * 32;
            for (int ui = 0; ui < ni; ui++) {
                int ddi = (pi == 0) ? (1 + 2 * ui) : (2 * ui);
                int si = (ddi >> 1) - 1;
                for (int uj = 0; uj < nj; uj++) {
                    int ddj = (pj == 0) ? (1 + 2 * uj) : (2 * uj);
                    int sj = (ddj >> 1) - 1;
                    const uint32_t goff = bufo + (uint32_t)(((1 + wrp + si) * 9 + 1 + sj) * 48);
                    uint32_t a0[4], a1[4];
                    LDSM4(a0, lb0 + goff);
                    LDSM4(a1, lb1 + goff);
                    const uint4* wt = wch + (ddi * 5 + ddj) * (8 * 32);
                    uint4 bf[4];
#pragma unroll
                    for (int p = 0; p < 4; p++) bf[p] = __ldg(wt + p * 32);
#pragma unroll
                    for (int p = 0; p < 4; p++) {
                        MMA2(acc[0][2 * p + 0], a0, bf[p].x, bf[p].y);
                        MMA2(acc[1][2 * p + 0], a1, bf[p].x, bf[p].y);
                        MMA2(acc[0][2 * p + 1], a0, bf[p].z, bf[p].w);
                        MMA2(acc[1][2 * p + 1], a1, bf[p].z, bf[p].w);
                    }
                }
            }
        }

#pragma unroll
        for (int mb = 0; mb < 2; mb++) {
#pragma unroll
            for (int nt = 0; nt < 8; nt++) {
                int co = co0 + nt * 8 + n_;
                float2 gg = *(const float2*)(G2 + c * 128 + co);
                float2 bb = *(const float2*)(B2 + c * 128 + co);
                float2 mm = *(const float2*)(M2 + c * 128 + co);
                float2 vv = *(const float2*)(V2 + c * 128 + co);
                float sx = rsqrtf(vv.x + 1e-3f) * gg.x;
                float sy = rsqrtf(vv.y + 1e-3f) * gg.y;
#pragma unroll
                for (int h = 0; h < 2; h++) {
                    int m = mb * 16 + g_ + h * 8;
                    int jx = m >> 2, s = m & 3;
                    if (jx < 7 && sok[s]) {
                        int oi = 2 * wrp + pi, oj = 2 * jx + pj;
                        float y0 = lrelu((acc[mb][nt][h * 2 + 0] - mm.x) * sx + bb.x);
                        float y1 = lrelu((acc[mb][nt][h * 2 + 1] - mm.y) * sy + bb.y);
                        *(__half2*)(g_a2 + ((size_t)samp[s] * 196 + oi * 14 + oj) * 128 + co) =
                            __halves2half2(__float2half(y0), __float2half(y1));
                    }
                }
            }
        }
    }
}

// =====================================================================
// conv3: 5x5 s2, 128 -> 1, tanh (fp16 inputs)
// =====================================================================
#define D_IN_B (196 * C2 * 2)
#define D_W_B  (25 * C2 * 4)

__global__ __launch_bounds__(256, 2) void k_conv3(
    const int* __restrict__ labels, const float* __restrict__ K3,
    float* __restrict__ out)
{
    extern __shared__ __align__(16) char smraw[];
    __half* in_h = (__half*)smraw;
    float*  w_s  = (float*)(smraw + D_IN_B);
    const int b = blockIdx.x;
    const int t = threadIdx.x;
    const int c = labels[b];

    const uint4* a2 = (const uint4*)(g_a2 + (size_t)b * (196 * C2));
    for (int q = t; q < 196 * 16; q += 256) ((uint4*)in_h)[q] = a2[q];
    const float4* k4 = (const float4*)(K3 + (size_t)c * 25 * C2);
    for (int q = t; q < 25 * 32; q += 256) ((float4*)w_s)[q] = k4[q];
    __syncthreads();

    for (int px = t; px < 784; px += 256) {
        const int oi = px / 28, oj = px - oi * 28;
        float acc = 0.f;
        for (int ddi = (oi & 1) ? 0 : 1; ddi < 5; ddi += 2) {
            int ii = (oi + ddi - 3) >> 1;
            if ((unsigned)ii >= 14u) continue;
            for (int ddj = (oj & 1) ? 0 : 1; ddj < 5; ddj += 2) {
                int jj = (oj + ddj - 3) >> 1;
                if ((unsigned)jj >= 14u) continue;
                const __half2* ip = (const __half2*)(in_h + (ii * 14 + jj) * C2);
                const float2* wp = (const float2*)(w_s + (ddi * 5 + ddj) * C2);
#pragma unroll 16
                for (int q = 0; q < 64; q++) {
                    float2 a = __half22float2(ip[q]);
                    float2 w = wp[q];
                    acc += a.x * w.x + a.y * w.y;
                }
            }
        }
        out[(size_t)b * 784 + px] = tanhf(acc);
    }
}

// =====================================================================
extern "C" void kernel_launch(void* const* d_in, const int* in_sizes, int n_in,
                              void* d_out, int out_size)
{
    const float* noise = (const float*)d_in[0];
    const int*   labels= (const int*)  d_in[1];
    const float* emb   = (const float*)d_in[2];
    const float* Wd    = (const float*)d_in[3];
    const float* bn1g  = (const float*)d_in[4];
    const float* bn1b  = (const float*)d_in[5];
    const float* bn1m  = (const float*)d_in[6];
    const float* bn1v  = (const float*)d_in[7];
    const float* K1    = (const float*)d_in[8];
    const float* G1    = (const float*)d_in[9];
    const float* B1    = (const float*)d_in[10];
    const float* M1    = (const float*)d_in[11];
    const float* V1    = (const float*)d_in[12];
    const float* K2    = (const float*)d_in[13];
    const float* G2    = (const float*)d_in[14];
    const float* B2    = (const float*)d_in[15];
    const float* M2    = (const float*)d_in[16];
    const float* V2    = (const float*)d_in[17];
    const float* K3    = (const float*)d_in[18];
    float* out = (float*)d_out;

    const int smB = 2 * A1_B;             // 47360
    const int smC = 2 * A2_B;             // 32000
    const int smD = D_IN_B + D_W_B;       // 62976
    cudaFuncSetAttribute(k_conv1, cudaFuncAttributeMaxDynamicSharedMemorySize, smB);
    cudaFuncSetAttribute(k_conv2, cudaFuncAttributeMaxDynamicSharedMemorySize, smC);
    cudaFuncSetAttribute(k_conv3, cudaFuncAttributeMaxDynamicSharedMemorySize, smD);

    k_packwd<<<dim3(98, 10), 256>>>(Wd);
    k_dense2<<<dim3(98, 32), 128>>>(noise, labels, emb, bn1g, bn1b, bn1m, bn1v);
    k_bucket<<<1, 512>>>(labels);
    k_packw1<<<dim3(25, 16, 10), 256>>>(K1);
    k_embw<<<dim3(25, 10), 256>>>(K1, emb);
    k_embe<<<dim3(49, 10), 256>>>(nullptr);
    k_conv1<<<dim3(32, 4, 10), 224, smB>>>(G1, B1, M1, V1);
    k_packw2<<<dim3(25, 16, 10), 256>>>(K2);
    k_conv2<<<dim3(32, 2, 10), 224, smC>>>(G2, B2, M2, V2);
    k_conv3<<<BATCH, 256, smD>>>(labels, K3, out);
}

// round 17
// speedup vs baseline: 1.0819x; 1.0489x over previous
#include <cuda_runtime.h>
#include <cuda_fp16.h>
#include <cstdint>

#define BATCH 512
#define NOISE 100
#define EMBD  50
#define NCLS  10
#define C1    256
#define C2    128

typedef unsigned long long ull;

// ---------------- scratch ----------------
__device__ __align__(16) __half g_a0[BATCH * 49 * 256];
__device__ __align__(16) __half g_a1[BATCH * 49 * 256];
__device__ __align__(16) __half g_a2[BATCH * 196 * C2];
__device__ __align__(16) float  g_embf[NCLS * 49 * 256];
__device__ __align__(16) float  g_embw[NCLS * 25 * 256];
__device__ __align__(16) uint4  g_W1[(size_t)NCLS * 16 * 25 * 16 * 32];
__device__ __align__(16) uint4  g_W2[(size_t)NCLS * 16 * 25 * 8 * 32];
__device__ __align__(16) uint4  g_Wd[(size_t)10 * 98 * 8 * 32];
__device__ int g_perm[BATCH];
__device__ int g_cnt[NCLS];
__device__ int g_off[NCLS];

__device__ __forceinline__ float lrelu(float x) { return x >= 0.f ? x : 0.3f * x; }

#define LDSM4(a, addr) asm volatile( \
    "ldmatrix.sync.aligned.m8n8.x4.shared.b16 {%0,%1,%2,%3}, [%4];" \
    : "=r"(a[0]), "=r"(a[1]), "=r"(a[2]), "=r"(a[3]) : "r"(addr))

#define MMA2(d, a, bx_, by_) asm volatile( \
    "mma.sync.aligned.m16n8k16.row.col.f32.f16.f16.f32 " \
    "{%0,%1,%2,%3}, {%4,%5,%6,%7}, {%8,%9}, {%0,%1,%2,%3};" \
    : "+f"(d[0]), "+f"(d[1]), "+f"(d[2]), "+f"(d[3]) \
    : "r"(a[0]), "r"(a[1]), "r"(a[2]), "r"(a[3]), "r"(bx_), "r"(by_))

#define CP_COMMIT() asm volatile("cp.async.commit_group;" ::: "memory")
#define CP_WAIT0()  asm volatile("cp.async.wait_group 0;" ::: "memory")

__device__ __forceinline__ void cp16(uint32_t saddr, const void* g) {
    asm volatile("cp.async.cg.shared.global [%0], [%1], 16;" :: "r"(saddr), "l"(g) : "memory");
}

__device__ __forceinline__ uint32_t h2pack(float a, float b) {
    __half2 p = __halves2half2(__float2half(a), __float2half(b));
    return *(uint32_t*)&p;
}

// =====================================================================
__global__ __launch_bounds__(512) void k_bucket(const int* __restrict__ labels)
{
    __shared__ int scnt[NCLS], scur[NCLS];
    int t = threadIdx.x;
    if (t < NCLS) scnt[t] = 0;
    __syncthreads();
    int c = labels[t];
    atomicAdd(&scnt[c], 1);
    __syncthreads();
    if (t == 0) {
        int run = 0;
        for (int k = 0; k < NCLS; k++) { g_off[k] = run; scur[k] = run; g_cnt[k] = scnt[k]; run += scnt[k]; }
    }
    __syncthreads();
    int pos = atomicAdd(&scur[c], 1);
    g_perm[pos] = t;
}

// =====================================================================
// dense weight pack
// =====================================================================
#define TPD 132
__global__ __launch_bounds__(256) void k_packwd(const float* __restrict__ Wd)
{
    __shared__ float tile[16 * TPD];
    int cb = blockIdx.x, ch = blockIdx.y;
    int t = threadIdx.x;
    for (int idx = t; idx < 512; idx += 256) {
        int r = idx >> 5, c4 = idx & 31;
        int k = ch * 16 + r;
        float4 v = make_float4(0.f, 0.f, 0.f, 0.f);
        if (k < 150) v = *(const float4*)(Wd + (size_t)k * 12544 + cb * 128 + c4 * 4);
        *(float4*)&tile[r * TPD + c4 * 4] = v;
    }
    __syncthreads();
    int lane = t & 31, wp = t >> 5;
    int k0 = (lane & 3) * 2, nq = lane >> 2;
    if (wp < 8) {
        int ntp = wp;
        int nA = ntp * 16 + nq;
        int nB = nA + 8;
        uint4 o;
        o.x = h2pack(tile[(k0 + 0) * TPD + nA], tile[(k0 + 1) * TPD + nA]);
        o.y = h2pack(tile[(k0 + 8) * TPD + nA], tile[(k0 + 9) * TPD + nA]);
        o.z = h2pack(tile[(k0 + 0) * TPD + nB], tile[(k0 + 1) * TPD + nB]);
        o.w = h2pack(tile[(k0 + 8) * TPD + nB], tile[(k0 + 9) * TPD + nB]);
        g_Wd[((size_t)(ch * 98 + cb) * 8 + ntp) * 32 + lane] = o;
    }
}

// =====================================================================
// dense on tensor cores
// =====================================================================
__global__ __launch_bounds__(128) void k_dense2(
    const float* __restrict__ noise, const int* __restrict__ labels,
    const float* __restrict__ emb,
    const float* __restrict__ bn_g,  const float* __restrict__ bn_b,
    const float* __restrict__ bn_m,  const float* __restrict__ bn_v)
{
    __shared__ __align__(16) __half xs[10 * 16 * 24];
    const int t = threadIdx.x;
    const int cb = blockIdx.x;
    const int b0 = blockIdx.y * 16;
    const int lane = t & 31, w = t >> 5;

    for (int idx = t; idx < 16 * 160; idx += 128) {
        int s = idx / 160, k = idx - s * 160;
        float val = 0.f;
        if (k < NOISE) val = noise[(b0 + s) * NOISE + k];
        else if (k < 150) val = emb[labels[b0 + s] * EMBD + (k - NOISE)];
        int ch = k >> 4, kl = k & 15;
        xs[(ch * 16 + s) * 24 + kl] = __float2half(val);
    }
    __syncthreads();

    const uint32_t a_u32 = (uint32_t)__cvta_generic_to_shared(xs);
    const int lm = lane & 15;
    const int koff = (lane >> 4) * 8;
    const uint32_t lb = a_u32 + (uint32_t)((lm * 24 + koff) * 2);

    float acc[4][4];
#pragma unroll
    for (int a = 0; a < 4; a++)
#pragma unroll
        for (int u = 0; u < 4; u++) acc[a][u] = 0.f;

#pragma unroll
    for (int ch = 0; ch < 10; ch++) {
        uint32_t a[4];
        LDSM4(a, lb + (uint32_t)(ch * 768));
#pragma unroll
        for (int pp = 0; pp < 2; pp++) {
            int ntp = w * 2 + pp;
            uint4 bf = __ldg(&g_Wd[((size_t)(ch * 98 + cb) * 8 + ntp) * 32 + lane]);
            MMA2(acc[pp * 2 + 0], a, bf.x, bf.y);
            MMA2(acc[pp * 2 + 1], a, bf.z, bf.w);
        }
    }

    const int g_ = lane >> 2;
    const int n_ = (lane & 3) * 2;
#pragma unroll
    for (int pp = 0; pp < 2; pp++) {
#pragma unroll
        for (int q = 0; q < 2; q++) {
            int aidx = pp * 2 + q;
            int j0 = cb * 128 + (w * 2 + pp) * 16 + q * 8 + n_;
            float2 gg = *(const float2*)(bn_g + j0);
            float2 bb = *(const float2*)(bn_b + j0);
            float2 mm = *(const float2*)(bn_m + j0);
            float2 vv = *(const float2*)(bn_v + j0);
            float sx = rsqrtf(vv.x + 1e-3f) * gg.x;
            float sy = rsqrtf(vv.y + 1e-3f) * gg.y;
#pragma unroll
            for (int h = 0; h < 2; h++) {
                int m = g_ + h * 8;
                float y0 = lrelu((acc[aidx][h * 2 + 0] - mm.x) * sx + bb.x);
                float y1 = lrelu((acc[aidx][h * 2 + 1] - mm.y) * sy + bb.y);
                *(__half2*)(g_a0 + (size_t)(b0 + m) * 12544 + j0) =
                    __halves2half2(__float2half(y0), __float2half(y1));
            }
        }
    }
}

// =====================================================================
// conv weight packing
// =====================================================================
#define TP1 260
__global__ __launch_bounds__(256) void k_packw1(const float* __restrict__ K1)
{
    __shared__ float tile[16 * TP1];
    int tap = blockIdx.x, chunk = blockIdx.y, c = blockIdx.z;
    int t = threadIdx.x;
    const float* src = K1 + (((size_t)c * 25 + tap) * 306 + chunk * 16) * 256;
    for (int idx = t; idx < 1024; idx += 256) {
        int r = idx >> 6, c4 = idx & 63;
        *(float4*)&tile[r * TP1 + c4 * 4] = ((const float4*)src)[idx];
    }
    __syncthreads();
    int lane = t & 31, wp = t >> 5;
    int k0 = (lane & 3) * 2, nq = lane >> 2;
    for (int ntp = wp; ntp < 16; ntp += 8) {
        int nA = ntp * 16 + nq;
        int nB = nA + 8;
        uint4 o;
        o.x = h2pack(tile[(k0 + 0) * TP1 + nA], tile[(k0 + 1) * TP1 + nA]);
        o.y = h2pack(tile[(k0 + 8) * TP1 + nA], tile[(k0 + 9) * TP1 + nA]);
        o.z = h2pack(tile[(k0 + 0) * TP1 + nB], tile[(k0 + 1) * TP1 + nB]);
        o.w = h2pack(tile[(k0 + 8) * TP1 + nB], tile[(k0 + 9) * TP1 + nB]);
        g_W1[((((size_t)c * 16 + chunk) * 25 + tap) * 16 + ntp) * 32 + lane] = o;
    }
}

#define TP2 132
__global__ __launch_bounds__(256) void k_packw2(const float* __restrict__ K2)
{
    __shared__ float tile[16 * TP2];
    int tap = blockIdx.x, chunk = blockIdx.y, c = blockIdx.z;
    int t = threadIdx.x;
    const float* src = K2 + (((size_t)c * 25 + tap) * 256 + chunk * 16) * 128;
    for (int idx = t; idx < 512; idx += 256) {
        int r = idx >> 5, c4 = idx & 31;
        *(float4*)&tile[r * TP2 + c4 * 4] = ((const float4*)src)[idx];
    }
    __syncthreads();
    int lane = t & 31, wp = t >> 5;
    int k0 = (lane & 3) * 2, nq = lane >> 2;
    if (wp < 8) {
        int ntp = wp;
        int nA = ntp * 16 + nq;
        int nB = nA + 8;
        uint4 o;
        o.x = h2pack(tile[(k0 + 0) * TP2 + nA], tile[(k0 + 1) * TP2 + nA]);
        o.y = h2pack(tile[(k0 + 8) * TP2 + nA], tile[(k0 + 9) * TP2 + nA]);
        o.z = h2pack(tile[(k0 + 0) * TP2 + nB], tile[(k0 + 1) * TP2 + nB]);
        o.w = h2pack(tile[(k0 + 8) * TP2 + nB], tile[(k0 + 9) * TP2 + nB]);
        g_W2[((((size_t)c * 16 + chunk) * 25 + tap) * 8 + ntp) * 32 + lane] = o;
    }
}

// =====================================================================
// emb fold
// =====================================================================
__global__ __launch_bounds__(256) void k_embw(
    const float* __restrict__ K1, const float* __restrict__ emb)
{
    __shared__ float es[EMBD];
    int tap = blockIdx.x, c = blockIdx.y, t = threadIdx.x;
    if (t < EMBD) es[t] = emb[c * EMBD + t];
    __syncthreads();
    const float* kb = K1 + (((size_t)c * 25 + tap) * 306 + 256) * 256 + t;
    float acc = 0.f;
#pragma unroll 10
    for (int e = 0; e < EMBD; e++) acc += es[e] * kb[(size_t)e * 256];
    g_embw[((size_t)c * 25 + tap) * 256 + t] = acc;
}

__global__ __launch_bounds__(256) void k_embe(const float* dummy)
{
    int p = blockIdx.x, c = blockIdx.y, t = threadIdx.x;
    int i = p / 7, j = p - 7 * i;
    float acc = 0.f;
    for (int di = 0; di < 5; di++) {
        int ii = i + di - 2; if ((unsigned)ii >= 7u) continue;
        for (int dj = 0; dj < 5; dj++) {
            int jj = j + dj - 2; if ((unsigned)jj >= 7u) continue;
            acc += g_embw[((size_t)c * 25 + di * 5 + dj) * 256 + t];
        }
    }
    g_embf[((size_t)c * 49 + p) * 256 + t] = acc;
}

// =====================================================================
// conv1: 4 samples/CTA, 64 co, 7 warps; register-pipelined weights
// =====================================================================
#define SPL1   2960
#define A1_FP  (4 * SPL1)
#define A1_B   (A1_FP * 2)

__global__ __launch_bounds__(224, 2) void k_conv1(
    const float* __restrict__ G1, const float* __restrict__ B1,
    const float* __restrict__ M1, const float* __restrict__ V1)
{
    extern __shared__ __align__(16) char smraw[];
    __half* A = (__half*)smraw;

    const int c = blockIdx.z;
    const int n_c = g_cnt[c];
    const int stile = blockIdx.x;
    if (stile * 4 >= n_c) return;
    const int by = blockIdx.y;
    const int co0 = by * 64;
    const int t = threadIdx.x, lane = t & 31, wrp = t >> 5;
    const int base = g_off[c];

    int samp[4]; bool sok[4];
#pragma unroll
    for (int s = 0; s < 4; s++) {
        int idx = stile * 4 + s;
        sok[s] = idx < n_c;
        samp[s] = g_perm[base + (idx < n_c ? idx : n_c - 1)];
    }

    const uint32_t a_u32 = (uint32_t)__cvta_generic_to_shared(A);
    const int lm = lane & 15;
    const int ljx = lm >> 2, ls = lm & 3;
    const int koff = (lane >> 4) * 8;
    const uint32_t lb0 = a_u32 + (uint32_t)((ls * SPL1 + ljx * 24 + koff) * 2);
    const uint32_t lb1 = a_u32 + (uint32_t)((ls * SPL1 + (ljx + 4) * 24 + koff) * 2);

    int rpos = 0; const __half* rsrc0 = nullptr;
    if (t < 196) {
        int rs = t / 49; int p = t - rs * 49;
        int pi_ = p / 7, pj_ = p - 7 * pi_;
        rpos = (rs * SPL1 + ((2 + pi_) * 11 + 2 + pj_) * 24) * 2;
        rsrc0 = g_a0 + ((size_t)samp[rs] * 49 + p) * 256;
    }

    for (int q = t; q < 2 * A1_FP / 8; q += 224) ((uint4*)A)[q] = make_uint4(0, 0, 0, 0);
    __syncthreads();

    float acc[2][8][4];
#pragma unroll
    for (int mb = 0; mb < 2; mb++)
#pragma unroll
        for (int nt = 0; nt < 8; nt++)
#pragma unroll
            for (int u = 0; u < 4; u++) acc[mb][nt][u] = 0.f;

    const uint4* wbase = g_W1 + ((size_t)c * 16 * 25 * 16 + (size_t)by * 4) * 32 + lane;

    if (t < 196) {
        uint32_t d = a_u32 + (uint32_t)rpos;
        cp16(d, rsrc0); cp16(d + 16, rsrc0 + 8);
    }
    CP_COMMIT();

    // register-pipeline prologue: chunk0 tap0 fragments
    uint4 bfc[4];
#pragma unroll
    for (int p = 0; p < 4; p++) bfc[p] = __ldg(wbase + p * 32);

    for (int chunk = 0; chunk < 16; chunk++) {
        CP_WAIT0();
        __syncthreads();
        if (chunk + 1 < 16) {
            if (t < 196) {
                uint32_t d = a_u32 + (uint32_t)(((chunk + 1) & 1) * A1_B) + (uint32_t)rpos;
                const __half* src = rsrc0 + (chunk + 1) * 16;
                cp16(d, src); cp16(d + 16, src + 8);
            }
            CP_COMMIT();
        }
        const uint32_t bufo = (uint32_t)((chunk & 1) * A1_B);
        const uint4* wch = wbase + (size_t)chunk * 25 * 16 * 32;

#pragma unroll
        for (int tap = 0; tap < 25; tap++) {
            const int di = tap / 5, dj = tap - 5 * di;
            // prefetch next tap (cross-chunk at tap 24)
            uint4 bfn[4];
            if (tap < 24) {
#pragma unroll
                for (int p = 0; p < 4; p++) bfn[p] = __ldg(wch + (tap + 1) * 512 + p * 32);
            } else if (chunk + 1 < 16) {
#pragma unroll
                for (int p = 0; p < 4; p++) bfn[p] = __ldg(wch + 25 * 512 + p * 32);
            }
            const uint32_t goff = bufo + (uint32_t)(((wrp + di) * 11 + dj) * 48);
            uint32_t a0[4], a1[4];
            LDSM4(a0, lb0 + goff);
            LDSM4(a1, lb1 + goff);
#pragma unroll
            for (int p = 0; p < 4; p++) {
                MMA2(acc[0][2 * p + 0], a0, bfc[p].x, bfc[p].y);
                MMA2(acc[1][2 * p + 0], a1, bfc[p].x, bfc[p].y);
                MMA2(acc[0][2 * p + 1], a0, bfc[p].z, bfc[p].w);
                MMA2(acc[1][2 * p + 1], a1, bfc[p].z, bfc[p].w);
            }
#pragma unroll
            for (int p = 0; p < 4; p++) bfc[p] = bfn[p];
        }
    }

    const int g_ = lane >> 2;
    const int n_ = (lane & 3) * 2;
#pragma unroll
    for (int mb = 0; mb < 2; mb++) {
#pragma unroll
        for (int nt = 0; nt < 8; nt++) {
            int co = co0 + nt * 8 + n_;
            float2 gg = *(const float2*)(G1 + c * 256 + co);
            float2 bb = *(const float2*)(B1 + c * 256 + co);
            float2 mm = *(const float2*)(M1 + c * 256 + co);
            float2 vv = *(const float2*)(V1 + c * 256 + co);
            float sx = rsqrtf(vv.x + 1e-3f) * gg.x;
            float sy = rsqrtf(vv.y + 1e-3f) * gg.y;
#pragma unroll
            for (int h = 0; h < 2; h++) {
                int m = mb * 16 + g_ + h * 8;
                int jx = m >> 2, s = m & 3;
                if (jx < 7 && sok[s]) {
                    int pos = wrp * 7 + jx;
                    float2 E = *(const float2*)(g_embf + ((size_t)c * 49 + pos) * 256 + co);
                    float y0 = lrelu((acc[mb][nt][h * 2 + 0] + E.x - mm.x) * sx + bb.x);
                    float y1 = lrelu((acc[mb][nt][h * 2 + 1] + E.y - mm.y) * sy + bb.y);
                    *(__half2*)(g_a1 + ((size_t)samp[s] * 49 + pos) * 256 + co) =
                        __halves2half2(__float2half(y0), __float2half(y1));
                }
            }
        }
    }
}

// =====================================================================
// conv2: parity-SPLIT grid (one parity per CTA), 4 samples/CTA, 64 co.
// blockIdx.y: bit0 = co half, bits[1:2] = parity. Register-pipelined weights.
// =====================================================================
#define SPL2   2000
#define A2_FP  (4 * SPL2)
#define A2_B   (A2_FP * 2)

__global__ __launch_bounds__(224, 2) void k_conv2(
    const float* __restrict__ G2, const float* __restrict__ B2,
    const float* __restrict__ M2, const float* __restrict__ V2)
{
    extern __shared__ __align__(16) char smraw[];
    __half* A = (__half*)smraw;

    const int c = blockIdx.z;
    const int n_c = g_cnt[c];
    const int stile = blockIdx.x;
    if (stile * 4 >= n_c) return;
    const int by = blockIdx.y & 1;
    const int pp = blockIdx.y >> 1;
    const int pi = pp >> 1, pj = pp & 1;
    const int co0 = by * 64;
    const int t = threadIdx.x, lane = t & 31, wrp = t >> 5;
    const int base = g_off[c];

    int samp[4]; bool sok[4];
#pragma unroll
    for (int s = 0; s < 4; s++) {
        int idx = stile * 4 + s;
        sok[s] = idx < n_c;
        samp[s] = g_perm[base + (idx < n_c ? idx : n_c - 1)];
    }

    const uint32_t a_u32 = (uint32_t)__cvta_generic_to_shared(A);
    const int lm = lane & 15;
    const int ljx = lm >> 2, ls = lm & 3;
    const int koff = (lane >> 4) * 8;
    const uint32_t lb0 = a_u32 + (uint32_t)((ls * SPL2 + ljx * 24 + koff) * 2);
    const uint32_t lb1 = a_u32 + (uint32_t)((ls * SPL2 + (ljx + 4) * 24 + koff) * 2);

    int rpos = 0; const __half* rsrc0 = nullptr;
    if (t < 196) {
        int rs = t / 49; int p = t - rs * 49;
        int pi_ = p / 7, pj_ = p - 7 * pi_;
        rpos = (rs * SPL2 + ((1 + pi_) * 9 + 1 + pj_) * 24) * 2;
        rsrc0 = g_a1 + ((size_t)samp[rs] * 49 + p) * 256;
    }

    for (int q = t; q < 2 * A2_FP / 8; q += 224) ((uint4*)A)[q] = make_uint4(0, 0, 0, 0);
    __syncthreads();

    // tap list for this parity
    const int ni = (pi == 0) ? 2 : 3, nj = (pj == 0) ? 2 : 3;
    const int nt_taps = ni * nj;
    int wofs[9]; uint32_t gofs[9];
    {
        int tc = 0;
        for (int ui = 0; ui < ni; ui++) {
            int ddi = (pi == 0) ? (1 + 2 * ui) : (2 * ui);
            int si = (ddi >> 1) - 1;
            for (int uj = 0; uj < nj; uj++) {
                int ddj = (pj == 0) ? (1 + 2 * uj) : (2 * uj);
                int sj = (ddj >> 1) - 1;
                wofs[tc] = (ddi * 5 + ddj) * 256;          // uint4 units (8*32)
                gofs[tc] = (uint32_t)(((1 + wrp + si) * 9 + 1 + sj) * 48);
                tc++;
            }
        }
    }

    const uint4* wcls = g_W2 + ((size_t)c * 16 * 25 * 8 + (size_t)by * 4) * 32 + lane;
    const int g_ = lane >> 2;
    const int n_ = (lane & 3) * 2;

    float acc[2][8][4];
#pragma unroll
    for (int mb = 0; mb < 2; mb++)
#pragma unroll
        for (int nt = 0; nt < 8; nt++)
#pragma unroll
            for (int u = 0; u < 4; u++) acc[mb][nt][u] = 0.f;

    if (t < 196) {
        uint32_t d = a_u32 + (uint32_t)rpos;
        cp16(d, rsrc0); cp16(d + 16, rsrc0 + 8);
    }
    CP_COMMIT();

    uint4 bfc[4];
#pragma unroll
    for (int p = 0; p < 4; p++) bfc[p] = __ldg(wcls + wofs[0] + p * 32);

    for (int chunk = 0; chunk < 16; chunk++) {
        CP_WAIT0();
        __syncthreads();
        if (chunk + 1 < 16) {
            if (t < 196) {
                uint32_t d = a_u32 + (uint32_t)(((chunk + 1) & 1) * A2_B) + (uint32_t)rpos;
                const __half* src = rsrc0 + (chunk + 1) * 16;
                cp16(d, src); cp16(d + 16, src + 8);
            }
            CP_COMMIT();
        }
        const uint32_t bufo = (uint32_t)((chunk & 1) * A2_B);
        const uint4* wch = wcls + (size_t)chunk * 25 * 256;

        for (int tt = 0; tt < nt_taps; tt++) {
            uint4 bfn[4];
            if (tt + 1 < nt_taps) {
#pragma unroll
                for (int p = 0; p < 4; p++) bfn[p] = __ldg(wch + wofs[tt + 1] + p * 32);
            } else if (chunk + 1 < 16) {
#pragma unroll
                for (int p = 0; p < 4; p++) bfn[p] = __ldg(wch + 25 * 256 + wofs[0] + p * 32);
            }
            const uint32_t goff = bufo + gofs[tt];
            uint32_t a0[4], a1[4];
            LDSM4(a0, lb0 + goff);
            LDSM4(a1, lb1 + goff);
#pragma unroll
            for (int p = 0; p < 4; p++) {
                MMA2(acc[0][2 * p + 0], a0, bfc[p].x, bfc[p].y);
                MMA2(acc[1][2 * p + 0], a1, bfc[p].x, bfc[p].y);
                MMA2(acc[0][2 * p + 1], a0, bfc[p].z, bfc[p].w);
                MMA2(acc[1][2 * p + 1], a1, bfc[p].z, bfc[p].w);
            }
#pragma unroll
            for (int p = 0; p < 4; p++) bfc[p] = bfn[p];
        }
    }

    // epilogue (this parity only) -> act2 fp16
#pragma unroll
    for (int mb = 0; mb < 2; mb++) {
#pragma unroll
        for (int nt = 0; nt < 8; nt++) {
            int co = co0 + nt * 8 + n_;
            float2 gg = *(const float2*)(G2 + c * 128 + co);
            float2 bb = *(const float2*)(B2 + c * 128 + co);
            float2 mm = *(const float2*)(M2 + c * 128 + co);
            float2 vv = *(const float2*)(V2 + c * 128 + co);
            float sx = rsqrtf(vv.x + 1e-3f) * gg.x;
            float sy = rsqrtf(vv.y + 1e-3f) * gg.y;
#pragma unroll
            for (int h = 0; h < 2; h++) {
                int m = mb * 16 + g_ + h * 8;
                int jx = m >> 2, s = m & 3;
                if (jx < 7 && sok[s]) {
                    int oi = 2 * wrp + pi, oj = 2 * jx + pj;
                    float y0 = lrelu((acc[mb][nt][h * 2 + 0] - mm.x) * sx + bb.x);
                    float y1 = lrelu((acc[mb][nt][h * 2 + 1] - mm.y) * sy + bb.y);
                    *(__half2*)(g_a2 + ((size_t)samp[s] * 196 + oi * 14 + oj) * 128 + co) =
                        __halves2half2(__float2half(y0), __float2half(y1));
                }
            }
        }
    }
}

// =====================================================================
// conv3: 5x5 s2, 128 -> 1, tanh (fp16 inputs)
// =====================================================================
#define D_IN_B (196 * C2 * 2)
#define D_W_B  (25 * C2 * 4)

__global__ __launch_bounds__(256, 2) void k_conv3(
    const int* __restrict__ labels, const float* __restrict__ K3,
    float* __restrict__ out)
{
    extern __shared__ __align__(16) char smraw[];
    __half* in_h = (__half*)smraw;
    float*  w_s  = (float*)(smraw + D_IN_B);
    const int b = blockIdx.x;
    const int t = threadIdx.x;
    const int c = labels[b];

    const uint4* a2 = (const uint4*)(g_a2 + (size_t)b * (196 * C2));
    for (int q = t; q < 196 * 16; q += 256) ((uint4*)in_h)[q] = a2[q];
    const float4* k4 = (const float4*)(K3 + (size_t)c * 25 * C2);
    for (int q = t; q < 25 * 32; q += 256) ((float4*)w_s)[q] = k4[q];
    __syncthreads();

    for (int px = t; px < 784; px += 256) {
        const int oi = px / 28, oj = px - oi * 28;
        float acc = 0.f;
        for (int ddi = (oi & 1) ? 0 : 1; ddi < 5; ddi += 2) {
            int ii = (oi + ddi - 3) >> 1;
            if ((unsigned)ii >= 14u) continue;
            for (int ddj = (oj & 1) ? 0 : 1; ddj < 5; ddj += 2) {
                int jj = (oj + ddj - 3) >> 1;
                if ((unsigned)jj >= 14u) continue;
                const __half2* ip = (const __half2*)(in_h + (ii * 14 + jj) * C2);
                const float2* wp = (const float2*)(w_s + (ddi * 5 + ddj) * C2);
#pragma unroll 16
                for (int q = 0; q < 64; q++) {
                    float2 a = __half22float2(ip[q]);
                    float2 w = wp[q];
                    acc += a.x * w.x + a.y * w.y;
                }
            }
        }
        out[(size_t)b * 784 + px] = tanhf(acc);
    }
}

// =====================================================================
extern "C" void kernel_launch(void* const* d_in, const int* in_sizes, int n_in,
                              void* d_out, int out_size)
{
    const float* noise = (const float*)d_in[0];
    const int*   labels= (const int*)  d_in[1];
    const float* emb   = (const float*)d_in[2];
    const float* Wd    = (const float*)d_in[3];
    const float* bn1g  = (const float*)d_in[4];
    const float* bn1b  = (const float*)d_in[5];
    const float* bn1m  = (const float*)d_in[6];
    const float* bn1v  = (const float*)d_in[7];
    const float* K1    = (const float*)d_in[8];
    const float* G1    = (const float*)d_in[9];
    const float* B1    = (const float*)d_in[10];
    const float* M1    = (const float*)d_in[11];
    const float* V1    = (const float*)d_in[12];
    const float* K2    = (const float*)d_in[13];
    const float* G2    = (const float*)d_in[14];
    const float* B2    = (const float*)d_in[15];
    const float* M2    = (const float*)d_in[16];
    const float* V2    = (const float*)d_in[17];
    const float* K3    = (const float*)d_in[18];
    float* out = (float*)d_out;

    const int smB = 2 * A1_B;             // 47360
    const int smC = 2 * A2_B;             // 32000
    const int smD = D_IN_B + D_W_B;       // 62976
    cudaFuncSetAttribute(k_conv1, cudaFuncAttributeMaxDynamicSharedMemorySize, smB);
    cudaFuncSetAttribute(k_conv2, cudaFuncAttributeMaxDynamicSharedMemorySize, smC);
    cudaFuncSetAttribute(k_conv3, cudaFuncAttributeMaxDynamicSharedMemorySize, smD);

    k_packwd<<<dim3(98, 10), 256>>>(Wd);
    k_dense2<<<dim3(98, 32), 128>>>(noise, labels, emb, bn1g, bn1b, bn1m, bn1v);
    k_bucket<<<1, 512>>>(labels);
    k_packw1<<<dim3(25, 16, 10), 256>>>(K1);
    k_embw<<<dim3(25, 10), 256>>>(K1, emb);
    k_embe<<<dim3(49, 10), 256>>>(nullptr);
    k_conv1<<<dim3(32, 4, 10), 224, smB>>>(G1, B1, M1, V1);
    k_packw2<<<dim3(25, 16, 10), 256>>>(K2);
    k_conv2<<<dim3(32, 8, 10), 224, smC>>>(G2, B2, M2, V2);
    k_conv3<<<BATCH, 256, smD>>>(labels, K3, out);
}